// round 7
// baseline (speedup 1.0000x reference)
#include <cuda_runtime.h>

#define TPB 512
#define NBLK 296                      // 2 CTAs/SM, all co-resident
#define BITEMS 4
#define BTILE 2048                    // bonds per tile
#define AITEMS 4
#define ATILE 2048                    // atoms per tile
#define MAX_BOND (1 << 22)
#define MAX_ATOM (1 << 20)
#define MAX_BT (MAX_BOND / BTILE)
#define MAX_AT (MAX_ATOM / ATILE)
#define MAX_GROUPS (1 << 21)          // 16-triple groups, up to 33.5M triples
#define CUTOFF 0.8f

// ---------------- scratch -----------------------------------------------
__device__ int g_deg[MAX_ATOM];
__device__ int2 g_ab[MAX_ATOM];       // {bondOff, deg}
__device__ int g_triStart[MAX_ATOM];
__device__ float g_keptF[MAX_BOND];
__device__ unsigned long long g_mask[MAX_BOND / 64];
__device__ volatile unsigned long long g_btStat[MAX_BT];  // lookback: flag<<62|cnt
__device__ volatile unsigned long long g_aStat[MAX_AT];   // flag<<62|tri<<22|deg
__device__ int2 g_grp[MAX_GROUPS];    // {off, d<<20|j<<10|kp} at group start
__device__ int g_T;
__device__ int g_bound[260];
__device__ volatile int g_barArrive;
__device__ volatile unsigned g_barGen;

// ---------------- helpers ------------------------------------------------
__device__ __forceinline__ void gridBarrier() {
    __syncthreads();
    if (threadIdx.x == 0) {
        __threadfence();
        unsigned gen = g_barGen;
        if (atomicAdd((int*)&g_barArrive, 1) == NBLK - 1) {
            g_barArrive = 0;
            __threadfence();
            g_barGen = gen + 1;
        } else {
            while (g_barGen == gen) __nanosleep(64);
        }
        __threadfence();
    }
    __syncthreads();
}

template <typename T>
__device__ __forceinline__ T warpIncl(T v) {
#pragma unroll
    for (int d = 1; d < 32; d <<= 1) {
        T n = __shfl_up_sync(0xffffffffu, v, d);
        if ((threadIdx.x & 31) >= d) v += n;
    }
    return v;
}

template <typename T>
__device__ __forceinline__ T blockExcl(T v, T* smem, T* total) {
    int lane = threadIdx.x & 31, w = threadIdx.x >> 5, nw = TPB >> 5;
    T inc = warpIncl(v);
    if (lane == 31) smem[w] = inc;
    __syncthreads();
    if (w == 0) {
        T x = (lane < nw) ? smem[lane] : (T)0;
        T xi = warpIncl(x);
        if (lane < nw) smem[lane] = xi - x;
        if (lane == nw - 1) smem[32] = xi;
    }
    __syncthreads();
    T res = inc - v + smem[w];
    T tot = smem[32];
    __syncthreads();
    if (total) *total = tot;
    return res;
}

// ---------------- the fused kernel ---------------------------------------
__global__ __launch_bounds__(TPB, 2) void fused(
    const int* __restrict__ src, const float* __restrict__ len,
    const int* __restrict__ n_atoms, int n_bond, int n_struct,
    float* __restrict__ out, int out_size) {
    __shared__ unsigned long long smLL[33];
    __shared__ unsigned long long smB;
    __shared__ int smStage[BTILE];

    int tid = threadIdx.x;
    int gtid = blockIdx.x * TPB + tid;
    const int gsize = NBLK * TPB;
    int nbt = (n_bond + BTILE - 1) / BTILE;

    int nA = 0;
    for (int s = 0; s < n_struct; s++) nA += n_atoms[s];
    int nAT = (nA + ATILE - 1) / ATILE;

    // ---- Phase A: zero deg + lookback statuses; struct bounds ----
    for (int i = gtid; i < nA; i += gsize) g_deg[i] = 0;
    for (int i = gtid; i < nbt; i += gsize) g_btStat[i] = 0ull;
    for (int i = gtid; i < nAT; i += gsize) g_aStat[i] = 0ull;
    if (gtid == 0) {
        int ns = n_struct < 256 ? n_struct : 256;
        int acc = 0;
        for (int s = 0; s < ns; s++) { g_bound[s] = acc; acc += n_atoms[s]; }
        g_bound[ns] = acc;
    }
    gridBarrier();

    // ---- Phase B: filter + degree atomics + lookback scan + scatter ----
    for (int t = blockIdx.x; t < nbt; t += NBLK) {
        int base = t * BTILE + tid * BITEMS;
        unsigned nib = 0;
        int curA = -1, curC = 0;
        if (base + BITEMS <= n_bond) {
            float4 l = *(const float4*)(len + base);
            int4 s = *(const int4*)(src + base);
            float lv[4] = {l.x, l.y, l.z, l.w};
            int sv[4] = {s.x, s.y, s.z, s.w};
#pragma unroll
            for (int i = 0; i < 4; i++) {
                if (lv[i] <= CUTOFF) {
                    nib |= 1u << i;
                    if (sv[i] == curA) curC++;
                    else { if (curC) atomicAdd(&g_deg[curA], curC); curA = sv[i]; curC = 1; }
                }
            }
        } else {
            for (int i = 0; i < BITEMS; i++) {
                int b = base + i;
                if (b < n_bond && len[b] <= CUTOFF) {
                    nib |= 1u << i;
                    int a = src[b];
                    if (a == curA) curC++;
                    else { if (curC) atomicAdd(&g_deg[curA], curC); curA = a; curC = 1; }
                }
            }
        }
        if (curC) atomicAdd(&g_deg[curA], curC);

        // mask word (16 threads x 4 bits)
        unsigned long long word = (unsigned long long)nib << ((tid & 15) * 4);
        word |= __shfl_xor_sync(0xffffffffu, word, 1);
        word |= __shfl_xor_sync(0xffffffffu, word, 2);
        word |= __shfl_xor_sync(0xffffffffu, word, 4);
        word |= __shfl_xor_sync(0xffffffffu, word, 8);
        if ((tid & 15) == 0) g_mask[t * 32 + (tid >> 4)] = word;

        int tot;
        int e = blockExcl<int>(__popc(nib), (int*)smLL, &tot);
#pragma unroll
        for (int i = 0; i < 4; i++)
            if ((nib >> i) & 1u) smStage[e++] = base + i;

        if (tid == 0) {
            unsigned long long ex = 0;
            if (t == 0) {
                g_btStat[0] = (2ull << 62) | (unsigned)tot;
            } else {
                g_btStat[t] = (1ull << 62) | (unsigned)tot;
                int p = t - 1;
                while (true) {
                    unsigned long long s = g_btStat[p];
                    unsigned st = (unsigned)(s >> 62);
                    if (!st) { __nanosleep(32); continue; }
                    ex += s & 0x3FFFFFFFFFFFFFFFull;
                    if (st == 2u) break;
                    p--;
                }
                g_btStat[t] = (2ull << 62) | (ex + (unsigned)tot);
            }
            smB = ex;
        }
        __syncthreads();
        int off = (int)smB;
        for (int i = tid; i < tot; i += TPB) g_keptF[off + i] = (float)smStage[i];
        __syncthreads();
    }
    gridBarrier();

    // ---- Phase C: atom lookback scan + ab/ts/n_triple_i + grp fill; tij ----
    int offTi = out_size - n_struct - nA;
    for (int at = blockIdx.x; at < nAT; at += NBLK) {
        int base = at * ATILE + tid * AITEMS;
        int dA[4];
        unsigned long long acc = 0;
#pragma unroll
        for (int i = 0; i < 4; i++) {
            int a = base + i;
            int d = (a < nA) ? g_deg[a] : 0;
            dA[i] = d;
            acc += ((unsigned long long)(unsigned)(d * (d - 1)) << 32) | (unsigned)d;
        }
        unsigned long long tot;
        unsigned long long e = blockExcl<unsigned long long>(acc, smLL, &tot);
        if (tid == 0) {
            unsigned aggD = (unsigned)(tot & 0xffffffffull);
            unsigned aggT = (unsigned)(tot >> 32);
            unsigned long long pay = ((unsigned long long)aggT << 22) | aggD;
            unsigned long long ex = 0;
            if (at == 0) {
                g_aStat[0] = (2ull << 62) | pay;
            } else {
                g_aStat[at] = (1ull << 62) | pay;
                int p = at - 1;
                while (true) {
                    unsigned long long s = g_aStat[p];
                    unsigned st = (unsigned)(s >> 62);
                    if (!st) { __nanosleep(32); continue; }
                    ex += s & 0x3FFFFFFFFFFFFFFFull;
                    if (st == 2u) break;
                    p--;
                }
                g_aStat[at] = (2ull << 62) | (ex + pay);
            }
            if (at == nAT - 1)
                g_T = (int)(((ex + pay) >> 22) & 0xffffffffull);
            smB = ex;
        }
        __syncthreads();
        unsigned long long exPay = smB;
        unsigned exD = (unsigned)(exPay & 0x3FFFFFull);
        unsigned exT = (unsigned)((exPay >> 22) & 0xffffffffull);
        unsigned long long run = (((unsigned long long)exT << 32) | exD) + e;
#pragma unroll
        for (int i = 0; i < 4; i++) {
            int a = base + i;
            if (a < nA) {
                int d = dA[i];
                int bo = (int)(run & 0xffffffffull);
                int ts = (int)(run >> 32);
                g_ab[a] = make_int2(bo, d);
                g_triStart[a] = ts;
                out[offTi + a] = (float)(d * (d - 1));
                if (d >= 2) {
                    int dm1 = d - 1;
                    int tri = d * dm1;
                    int g0 = (ts + 15) >> 4, g1 = (ts + tri + 15) >> 4;
                    if (g0 < g1) {
                        int local = (g0 << 4) - ts;
                        int j = local / dm1;
                        int kp = local - j * dm1;
                        int dbits = d << 20;
                        for (int g = g0; g < g1; g++) {
                            __stcs(&g_grp[g], make_int2(bo, dbits | (j << 10) | kp));
                            kp += 16;
                            while (kp >= dm1) { kp -= dm1; j++; }
                        }
                    }
                }
                run += ((unsigned long long)(unsigned)(d * (d - 1)) << 32) | (unsigned)d;
            }
        }
        __syncthreads();
    }

    // tij (deg final after Phase B barrier)
    int offTij = out_size - n_struct - nA - n_bond;
    int nBG = (n_bond + 3) >> 2;
    for (int q = gtid; q < nBG; q += gsize) {
        int b0 = q * 4;
        unsigned long long w = g_mask[b0 >> 6];
        unsigned nib = (unsigned)(w >> (b0 & 63)) & 0xFu;
        if (b0 + 4 <= n_bond) {
            int4 s = *(const int4*)(src + b0);
            float4 r;
            r.x = (nib & 1u) ? (float)(g_deg[s.x] - 1) : 0.0f;
            r.y = (nib & 2u) ? (float)(g_deg[s.y] - 1) : 0.0f;
            r.z = (nib & 4u) ? (float)(g_deg[s.z] - 1) : 0.0f;
            r.w = (nib & 8u) ? (float)(g_deg[s.w] - 1) : 0.0f;
            __stcs((float4*)(out + offTij + b0), r);
        } else {
            for (int i = 0; b0 + i < n_bond; i++)
                out[offTij + b0 + i] =
                    ((nib >> i) & 1u) ? (float)(g_deg[src[b0 + i]] - 1) : 0.0f;
        }
    }
    gridBarrier();

    // ---- Phase D: struct sums + pair emission (16 triples / group) ----
    int T = g_T;
    if (gtid < n_struct) {
        int lo = g_bound[gtid], hi = g_bound[gtid + 1];
        int vlo = (lo >= nA) ? T : g_triStart[lo];
        int vhi = (hi >= nA) ? T : g_triStart[hi];
        out[out_size - n_struct + gtid] = (float)(vhi - vlo);
    }
    int nG = (T + 15) >> 4;
    for (int g = gtid; g < nG; g += gsize) {
        int t0 = g << 4;
        int2 rec = __ldcs(&g_grp[g]);
        int off = rec.x;
        int kp = rec.y & 1023;
        int j = (rec.y >> 10) & 1023;
        int d = ((unsigned)rec.y) >> 20;
        int dm1 = d - 1;
        if (t0 + 16 <= T) {
#pragma unroll
            for (int b = 0; b < 2; b++) {
                int idxj[8], idxk[8];
#pragma unroll
                for (int i = 0; i < 8; i++) {
                    idxj[i] = off + j;
                    idxk[i] = off + kp + (kp >= j);
                    if (b * 8 + i < 15) {
                        if (++kp == dm1) {
                            kp = 0;
                            if (++j == d) {
                                int t = t0 + b * 8 + i + 1;
                                int lo = 0, hi = nA - 1;
                                while (lo < hi) {
                                    int mid = (lo + hi + 1) >> 1;
                                    if (g_triStart[mid] <= t) lo = mid; else hi = mid - 1;
                                }
                                int2 ab = g_ab[lo];
                                off = ab.x; d = ab.y; dm1 = d - 1; j = 0; kp = 0;
                            }
                        }
                    }
                }
                float4 o0, o1, o2, o3;
                o0.x = __ldg(&g_keptF[idxj[0]]); o0.y = __ldg(&g_keptF[idxk[0]]);
                o0.z = __ldg(&g_keptF[idxj[1]]); o0.w = __ldg(&g_keptF[idxk[1]]);
                o1.x = __ldg(&g_keptF[idxj[2]]); o1.y = __ldg(&g_keptF[idxk[2]]);
                o1.z = __ldg(&g_keptF[idxj[3]]); o1.w = __ldg(&g_keptF[idxk[3]]);
                o2.x = __ldg(&g_keptF[idxj[4]]); o2.y = __ldg(&g_keptF[idxk[4]]);
                o2.z = __ldg(&g_keptF[idxj[5]]); o2.w = __ldg(&g_keptF[idxk[5]]);
                o3.x = __ldg(&g_keptF[idxj[6]]); o3.y = __ldg(&g_keptF[idxk[6]]);
                o3.z = __ldg(&g_keptF[idxj[7]]); o3.w = __ldg(&g_keptF[idxk[7]]);
                float4* o4 = (float4*)(out + 2 * t0 + b * 16);
                __stcs(o4 + 0, o0);
                __stcs(o4 + 1, o1);
                __stcs(o4 + 2, o2);
                __stcs(o4 + 3, o3);
            }
        } else {
            for (int t = t0; t < T; t++) {
                out[2 * t] = g_keptF[off + j];
                out[2 * t + 1] = g_keptF[off + kp + (kp >= j)];
                if (t + 1 < T) {
                    if (++kp == dm1) {
                        kp = 0;
                        if (++j == d) {
                            int tt = t + 1;
                            int lo = 0, hi = nA - 1;
                            while (lo < hi) {
                                int mid = (lo + hi + 1) >> 1;
                                if (g_triStart[mid] <= tt) lo = mid; else hi = mid - 1;
                            }
                            int2 ab = g_ab[lo];
                            off = ab.x; d = ab.y; dm1 = d - 1; j = 0; kp = 0;
                        }
                    }
                }
            }
        }
    }
}

// ---------------- launch --------------------------------------------------
extern "C" void kernel_launch(void* const* d_in, const int* in_sizes, int n_in,
                              void* d_out, int out_size) {
    const int* src = (const int*)d_in[0];
    const float* len = (const float*)d_in[1];
    const int* n_atoms = (const int*)d_in[2];
    int n_bond = in_sizes[0];
    int n_struct = in_sizes[2];
    fused<<<NBLK, TPB>>>(src, len, n_atoms, n_bond, n_struct, (float*)d_out,
                         out_size);
}

// round 8
// speedup vs baseline: 1.2843x; 1.2843x over previous
#include <cuda_runtime.h>

#define TPB 512
#define NBLK 296                      // 2 CTAs/SM, all co-resident
#define BITEMS 4
#define BTILE 2048                    // bonds per filter tile
#define AITEMS 4
#define ATILE 2048                    // atoms per tile
#define MAX_BOND (1 << 22)
#define MAX_ATOM (1 << 20)
#define MAX_BT (MAX_BOND / BTILE)
#define MAX_AT (MAX_ATOM / ATILE)
#define CUTOFF 0.8f

#define NTRI 10240                    // triples per P7 block-tile
#define BOND_CAP 14336
#define ATOM_CAP 5128
#define SM_BONDS_OFF 0
#define SM_TS_OFF (BOND_CAP * 4)                       // 57344
#define SM_PK_OFF (SM_TS_OFF + ATOM_CAP * 4)           // 77856
#define DYN_SMEM (SM_PK_OFF + ATOM_CAP * 4)            // 98368

// ---------------- scratch ---------------------------------------------------
__device__ int g_deg[MAX_ATOM];
__device__ int2 g_ab[MAX_ATOM];       // {bondOff, deg}
__device__ int g_triStart[MAX_ATOM];
__device__ float g_keptF[MAX_BOND];
__device__ unsigned long long g_mask[MAX_BOND / 64];
__device__ int g_tileCnt[MAX_BT];
__device__ int g_tileOff[MAX_BT];
__device__ unsigned long long g_atPack[MAX_AT];
__device__ unsigned long long g_atPackOff[MAX_AT];
__device__ int g_T;
__device__ int g_bound[260];
__device__ volatile int g_barArrive;
__device__ volatile unsigned g_barGen;

// ---------------- helpers ----------------------------------------------------
__device__ __forceinline__ void gridBarrier() {
    __syncthreads();
    if (threadIdx.x == 0) {
        __threadfence();
        unsigned gen = g_barGen;
        if (atomicAdd((int*)&g_barArrive, 1) == NBLK - 1) {
            g_barArrive = 0;
            __threadfence();
            g_barGen = gen + 1;
        } else {
            while (g_barGen == gen) __nanosleep(64);
        }
        __threadfence();
    }
    __syncthreads();
}

template <typename T>
__device__ __forceinline__ T warpIncl(T v) {
#pragma unroll
    for (int d = 1; d < 32; d <<= 1) {
        T n = __shfl_up_sync(0xffffffffu, v, d);
        if ((threadIdx.x & 31) >= d) v += n;
    }
    return v;
}

template <typename T>
__device__ __forceinline__ T blockExcl(T v, T* smem, T* total) {
    int lane = threadIdx.x & 31, w = threadIdx.x >> 5, nw = TPB >> 5;
    T inc = warpIncl(v);
    if (lane == 31) smem[w] = inc;
    __syncthreads();
    if (w == 0) {
        T x = (lane < nw) ? smem[lane] : (T)0;
        T xi = warpIncl(x);
        if (lane < nw) smem[lane] = xi - x;
        if (lane == nw - 1) smem[32] = xi;
    }
    __syncthreads();
    T res = inc - v + smem[w];
    T tot = smem[32];
    __syncthreads();
    if (total) *total = tot;
    return res;
}

// largest a in [0,nA) with g_triStart[a] <= t  (ties -> largest index = owner)
__device__ __forceinline__ int searchAtomG(int t, int nA) {
    int lo = 0, hi = nA - 1;
    while (lo < hi) {
        int mid = (lo + hi + 1) >> 1;
        if (g_triStart[mid] <= t) lo = mid; else hi = mid - 1;
    }
    return lo;
}

// ---------------- the fused kernel -------------------------------------------
__global__ __launch_bounds__(TPB, 2) void fused(
    const int* __restrict__ src, const float* __restrict__ len,
    const int* __restrict__ n_atoms, int n_bond, int n_struct,
    float* __restrict__ out, int out_size) {
    extern __shared__ char dynS[];
    float* smBonds = (float*)(dynS + SM_BONDS_OFF);
    int* smTS = (int*)(dynS + SM_TS_OFF);
    int* smPK = (int*)(dynS + SM_PK_OFF);
    int* smStage = (int*)dynS;  // phase D only (8KB of bond region)
    __shared__ unsigned long long smLL[33];
    __shared__ int smInfo[4];   // nKept, nBond, ovf

    int tid = threadIdx.x;
    int gtid = blockIdx.x * TPB + tid;
    const int gsize = NBLK * TPB;
    int nbt = (n_bond + BTILE - 1) / BTILE;

    int nA = 0;
    for (int s = 0; s < n_struct; s++) nA += n_atoms[s];
    int nAT = (nA + ATILE - 1) / ATILE;

    // ---- A: zero deg; struct bounds ----
    for (int i = gtid; i < nA; i += gsize) g_deg[i] = 0;
    if (gtid == 0) {
        int ns = n_struct < 256 ? n_struct : 256;
        int acc = 0;
        for (int s = 0; s < ns; s++) { g_bound[s] = acc; acc += n_atoms[s]; }
        g_bound[ns] = acc;
    }
    gridBarrier();

    // ---- B: filter (mask + tile counts + run-aggregated degrees) ----
    for (int t = blockIdx.x; t < nbt; t += NBLK) {
        int base = t * BTILE + tid * BITEMS;
        unsigned nib = 0;
        int curA = -1, curC = 0;
        if (base + BITEMS <= n_bond) {
            float4 l = *(const float4*)(len + base);
            int4 s = *(const int4*)(src + base);
            float lv[4] = {l.x, l.y, l.z, l.w};
            int sv[4] = {s.x, s.y, s.z, s.w};
#pragma unroll
            for (int i = 0; i < 4; i++) {
                if (lv[i] <= CUTOFF) {
                    nib |= 1u << i;
                    if (sv[i] == curA) curC++;
                    else { if (curC) atomicAdd(&g_deg[curA], curC); curA = sv[i]; curC = 1; }
                }
            }
        } else {
            for (int i = 0; i < BITEMS; i++) {
                int b = base + i;
                if (b < n_bond && len[b] <= CUTOFF) {
                    nib |= 1u << i;
                    int a = src[b];
                    if (a == curA) curC++;
                    else { if (curC) atomicAdd(&g_deg[curA], curC); curA = a; curC = 1; }
                }
            }
        }
        if (curC) atomicAdd(&g_deg[curA], curC);
        unsigned long long word = (unsigned long long)nib << ((tid & 15) * 4);
        word |= __shfl_xor_sync(0xffffffffu, word, 1);
        word |= __shfl_xor_sync(0xffffffffu, word, 2);
        word |= __shfl_xor_sync(0xffffffffu, word, 4);
        word |= __shfl_xor_sync(0xffffffffu, word, 8);
        if ((tid & 15) == 0) g_mask[t * 32 + (tid >> 4)] = word;
        int tot;
        blockExcl<int>(__popc(nib), (int*)smLL, &tot);
        if (tid == 0) g_tileCnt[t] = tot;
    }
    gridBarrier();

    // ---- C: block0 scans bond-tile counts ----
    if (blockIdx.x == 0) {
        int carry = 0;
        for (int b0 = 0; b0 < nbt; b0 += TPB) {
            int i = b0 + tid;
            int v = (i < nbt) ? g_tileCnt[i] : 0;
            int tot;
            int e = blockExcl<int>(v, (int*)smLL, &tot);
            if (i < nbt) g_tileOff[i] = carry + e;
            carry += tot;
        }
    }
    gridBarrier();

    // ---- D: scatter keptF + tij + atom-tile sums ----
    for (int t = blockIdx.x; t < nbt; t += NBLK) {
        int base = t * BTILE + tid * BITEMS;
        unsigned nib = 0;
        if (base < n_bond) {
            unsigned long long w = g_mask[t * 32 + (tid >> 4)];
            nib = (unsigned)(w >> ((tid & 15) * 4)) & 0xFu;
        }
        int tot;
        int e = blockExcl<int>(__popc(nib), (int*)smLL, &tot);
#pragma unroll
        for (int i = 0; i < 4; i++)
            if ((nib >> i) & 1u) smStage[e++] = base + i;
        __syncthreads();
        int off = g_tileOff[t];
        for (int i = tid; i < tot; i += TPB) g_keptF[off + i] = (float)smStage[i];
        __syncthreads();
    }
    int offTij = out_size - n_struct - nA - n_bond;
    int nBG = (n_bond + 3) >> 2;
    for (int q = gtid; q < nBG; q += gsize) {
        int b0 = q * 4;
        unsigned long long w = g_mask[b0 >> 6];
        unsigned nib = (unsigned)(w >> (b0 & 63)) & 0xFu;
        if (b0 + 4 <= n_bond) {
            int4 s = *(const int4*)(src + b0);
            float4 r;
            r.x = (nib & 1u) ? (float)(g_deg[s.x] - 1) : 0.0f;
            r.y = (nib & 2u) ? (float)(g_deg[s.y] - 1) : 0.0f;
            r.z = (nib & 4u) ? (float)(g_deg[s.z] - 1) : 0.0f;
            r.w = (nib & 8u) ? (float)(g_deg[s.w] - 1) : 0.0f;
            __stcs((float4*)(out + offTij + b0), r);
        } else {
            for (int i = 0; b0 + i < n_bond; i++)
                out[offTij + b0 + i] =
                    ((nib >> i) & 1u) ? (float)(g_deg[src[b0 + i]] - 1) : 0.0f;
        }
    }
    for (int t = blockIdx.x; t < nAT; t += NBLK) {
        int base = t * ATILE + tid * AITEMS;
        unsigned long long acc = 0;
#pragma unroll
        for (int i = 0; i < 4; i++) {
            int a = base + i;
            int d = (a < nA) ? g_deg[a] : 0;
            acc += ((unsigned long long)(unsigned)(d * (d - 1)) << 32) | (unsigned)d;
        }
        unsigned long long tot;
        blockExcl<unsigned long long>(acc, smLL, &tot);
        if (tid == 0) g_atPack[t] = tot;
    }
    gridBarrier();

    // ---- E: block0 scans atom-tile sums ----
    if (blockIdx.x == 0) {
        unsigned long long carry = 0;
        for (int b0 = 0; b0 < nAT; b0 += TPB) {
            int i = b0 + tid;
            unsigned long long v = (i < nAT) ? g_atPack[i] : 0ull;
            unsigned long long tot;
            unsigned long long e = blockExcl<unsigned long long>(v, smLL, &tot);
            if (i < nAT) g_atPackOff[i] = carry + e;
            carry += tot;
        }
        if (tid == 0) g_T = (int)(carry >> 32);
    }
    gridBarrier();

    // ---- F: per-atom CSR offsets, triStart, n_triple_i ----
    int offTi = out_size - n_struct - nA;
    for (int t = blockIdx.x; t < nAT; t += NBLK) {
        int base = t * ATILE + tid * AITEMS;
        int dA[4];
        unsigned long long acc = 0;
#pragma unroll
        for (int i = 0; i < 4; i++) {
            int a = base + i;
            int d = (a < nA) ? g_deg[a] : 0;
            dA[i] = d;
            acc += ((unsigned long long)(unsigned)(d * (d - 1)) << 32) | (unsigned)d;
        }
        unsigned long long e =
            blockExcl<unsigned long long>(acc, smLL, (unsigned long long*)0);
        unsigned long long run = g_atPackOff[t] + e;
#pragma unroll
        for (int i = 0; i < 4; i++) {
            int a = base + i;
            if (a < nA) {
                int d = dA[i];
                g_ab[a] = make_int2((int)(run & 0xffffffffull), d);
                g_triStart[a] = (int)(run >> 32);
                out[offTi + a] = (float)(d * (d - 1));
                run += ((unsigned long long)(unsigned)(d * (d - 1)) << 32) | (unsigned)d;
            }
        }
    }
    gridBarrier();

    // ---- G: struct sums + smem-tiled pair emission ----
    int T = g_T;
    if (gtid < n_struct) {
        int lo = g_bound[gtid], hi = g_bound[gtid + 1];
        int vlo = (lo >= nA) ? T : g_triStart[lo];
        int vhi = (hi >= nA) ? T : g_triStart[hi];
        out[out_size - n_struct + gtid] = (float)(vhi - vlo);
    }
    int nT = (T + NTRI - 1) / NTRI;
    for (int tile = blockIdx.x; tile < nT; tile += NBLK) {
        int t0 = tile * NTRI;
        int t1 = min(t0 + NTRI, T);

        // Build smem atom table + bond cache.
        int aLo = searchAtomG(t0, nA);
        int aEnd = searchAtomG(t1 - 1, nA);
        if (tid == 0) { smInfo[0] = 0; smInfo[1] = 0; smInfo[2] = 0; }
        __syncthreads();
        for (int s0 = aLo; s0 <= aEnd; s0 += TPB) {
            int a = s0 + tid;
            int d = 0, ts = 0, off = 0;
            if (a <= aEnd) {
                int2 ab = g_ab[a];
                d = ab.y; off = ab.x;
                ts = g_triStart[a];
            }
            int keep = (a <= aEnd && d >= 2);
            if (keep && d > 2047) smInfo[2] = 1;
            int dcl = keep ? min(d, 2047) : 0;
            int pack = keep ? ((1 << 16) | dcl) : 0;
            int tot;
            int e = blockExcl<int>(pack, (int*)smLL, &tot);
            int aSlot = smInfo[0] + (e >> 16);
            int bSlot = smInfo[1] + (e & 0xFFFF);
            if (keep) {
                if (aSlot < ATOM_CAP - 1 && bSlot + d <= BOND_CAP && d <= 2047) {
                    smTS[aSlot] = ts;
                    smPK[aSlot] = (bSlot << 11) | d;
                    for (int i = 0; i < d; i++) smBonds[bSlot + i] = g_keptF[off + i];
                } else {
                    smInfo[2] = 1;
                }
            }
            __syncthreads();
            if (tid == 0) { smInfo[0] += tot >> 16; smInfo[1] += tot & 0xFFFF; }
            __syncthreads();
        }
        int nKept = smInfo[0];
        int ovf = smInfo[2];
        if (tid == 0 && !ovf) smTS[nKept] = 0x7FFFFFFF;
        __syncthreads();

        int u0 = t0 + tid * 2;
        if (!ovf) {
            if (u0 < t1) {
                int lo = 0, hi = nKept - 1;
                while (lo < hi) {
                    int m = (lo + hi + 1) >> 1;
                    if (smTS[m] <= u0) lo = m; else hi = m - 1;
                }
                int ai = lo;
#pragma unroll 1
                for (int it = 0; it < NTRI / (TPB * 2); it++) {
                    int uu = t0 + it * (TPB * 2) + tid * 2;
                    if (uu >= t1) break;
                    while (smTS[ai + 1] <= uu) ai++;
                    int pk = smPK[ai];
                    int off = pk >> 11, d = pk & 2047, dm1 = d - 1;
                    int local = uu - smTS[ai];
                    int j = local / dm1;
                    int kp = local - j * dm1;
                    float4 v;
                    v.x = smBonds[off + j];
                    v.y = smBonds[off + kp + (kp >= j)];
                    if (uu + 1 < t1) {
                        if (uu + 1 >= smTS[ai + 1]) {
                            int pk2 = smPK[ai + 1];
                            int of2 = pk2 >> 11;
                            v.z = smBonds[of2];
                            v.w = smBonds[of2 + 1];
                        } else {
                            int kp2 = kp + 1, j2 = j;
                            if (kp2 == dm1) { kp2 = 0; j2++; }
                            v.z = smBonds[off + j2];
                            v.w = smBonds[off + kp2 + (kp2 >= j2)];
                        }
                        __stcs((float4*)(out + 2 * uu), v);
                    } else {
                        *(float2*)(out + 2 * uu) = make_float2(v.x, v.y);
                    }
                }
            }
        } else {
            // Rare fallback: process tile straight from global memory.
            if (u0 < t1) {
                int ai = searchAtomG(u0, nA);
#pragma unroll 1
                for (int it = 0; it < NTRI / (TPB * 2); it++) {
                    int uu = t0 + it * (TPB * 2) + tid * 2;
                    if (uu >= t1) break;
                    while (ai + 1 < nA && g_triStart[ai + 1] <= uu) ai++;
                    int2 ab = g_ab[ai];
                    int off = ab.x, d = ab.y, dm1 = d - 1;
                    int local = uu - g_triStart[ai];
                    int j = local / dm1;
                    int kp = local - j * dm1;
                    float4 v;
                    v.x = g_keptF[off + j];
                    v.y = g_keptF[off + kp + (kp >= j)];
                    if (uu + 1 < t1) {
                        int end = g_triStart[ai] + d * dm1;
                        if (uu + 1 >= end) {
                            int a2 = ai + 1;
                            while (g_ab[a2].y < 2) a2++;
                            int2 ab2 = g_ab[a2];
                            v.z = g_keptF[ab2.x];
                            v.w = g_keptF[ab2.x + 1];
                        } else {
                            int kp2 = kp + 1, j2 = j;
                            if (kp2 == dm1) { kp2 = 0; j2++; }
                            v.z = g_keptF[off + j2];
                            v.w = g_keptF[off + kp2 + (kp2 >= j2)];
                        }
                        __stcs((float4*)(out + 2 * uu), v);
                    } else {
                        *(float2*)(out + 2 * uu) = make_float2(v.x, v.y);
                    }
                }
            }
        }
        __syncthreads();
    }
}

// ---------------- launch ------------------------------------------------------
extern "C" void kernel_launch(void* const* d_in, const int* in_sizes, int n_in,
                              void* d_out, int out_size) {
    const int* src = (const int*)d_in[0];
    const float* len = (const float*)d_in[1];
    const int* n_atoms = (const int*)d_in[2];
    int n_bond = in_sizes[0];
    int n_struct = in_sizes[2];
    cudaFuncSetAttribute(fused, cudaFuncAttributeMaxDynamicSharedMemorySize,
                         DYN_SMEM);
    fused<<<NBLK, TPB, DYN_SMEM>>>(src, len, n_atoms, n_bond, n_struct,
                                   (float*)d_out, out_size);
}